// round 1
// baseline (speedup 1.0000x reference)
#include <cuda_runtime.h>
#include <math.h>

#define BB 16
#define LC 1024
#define LQ 512
#define DD 512
#define NEG_INF_F (-1e30f)

// ---------------- scratch (static __device__ arrays; no allocations) --------
__device__ float g_c1[BB * LC];             //  64 KB
__device__ float g_q2[BB * LQ];             //  32 KB
__device__ float g_S [BB * LC * LQ];        //  32 MB
__device__ float g_S1[BB * LC * LQ];        //  32 MB
__device__ float g_S2[BB * LC * LQ];        //  32 MB
__device__ float g_A [BB * LC * DD];        //  32 MB
__device__ float g_T [BB * LQ * DD];        //  16 MB
__device__ float g_Bm[BB * LC * DD];        //  32 MB

// ---------------- helpers ---------------------------------------------------
__device__ __forceinline__ void mm16(const float (*As)[64], const float (*Bs)[64],
                                     float acc[4][4], int ty, int tx) {
#pragma unroll
    for (int kk = 0; kk < 16; kk++) {
        const float4 av = *(const float4*)(&As[kk][ty << 2]);
        const float4 bv = *(const float4*)(&Bs[kk][tx << 2]);
        const float a[4] = {av.x, av.y, av.z, av.w};
        const float b[4] = {bv.x, bv.y, bv.z, bv.w};
#pragma unroll
        for (int i = 0; i < 4; i++)
#pragma unroll
            for (int j = 0; j < 4; j++)
                acc[i][j] = fmaf(a[i], b[j], acc[i][j]);
    }
}

// ---------------- K1: row dot products (c1 = C.w1, q2 = Q.w2) ---------------
__global__ void rowdot_kernel(const float* __restrict__ X, const float* __restrict__ w,
                              int which, int nrows) {
    float* out = which ? g_q2 : g_c1;
    int gw = (blockIdx.x * blockDim.x + threadIdx.x) >> 5;
    int lane = threadIdx.x & 31;
    if (gw >= nrows) return;
    const float* row = X + (size_t)gw * DD;
    float s = 0.f;
#pragma unroll 4
    for (int k = lane; k < DD; k += 32) s = fmaf(row[k], w[k], s);
#pragma unroll
    for (int o = 16; o; o >>= 1) s += __shfl_xor_sync(0xffffffffu, s, o);
    if (lane == 0) out[gw] = s;
}

// ---------------- K2: S = (C * w3) @ Q^T + c1 + q2  (NT GEMM) ---------------
__global__ __launch_bounds__(256) void gemm_S_kernel(const float* __restrict__ Cin,
                                                     const float* __restrict__ Qin,
                                                     const float* __restrict__ w) {
    __shared__ float As[16][64];
    __shared__ float Bs[16][64];
    const float* w3 = w + 2 * DD;
    int b = blockIdx.z;
    int row0 = blockIdx.y << 6, col0 = blockIdx.x << 6;
    const float* Ag = Cin + (size_t)b * LC * DD;
    const float* Bg = Qin + (size_t)b * LQ * DD;
    int tid = threadIdx.x;
    int ty = tid >> 4, tx = tid & 15;
    int lm = tid >> 2, lk = (tid & 3) << 2;
    float acc[4][4] = {};
    for (int k0 = 0; k0 < DD; k0 += 16) {
        float4 a4 = *(const float4*)(Ag + (size_t)(row0 + lm) * DD + k0 + lk);
        float4 w4 = *(const float4*)(w3 + k0 + lk);
        a4.x *= w4.x; a4.y *= w4.y; a4.z *= w4.z; a4.w *= w4.w;
        float4 b4 = *(const float4*)(Bg + (size_t)(col0 + lm) * DD + k0 + lk);
        As[lk + 0][lm] = a4.x; As[lk + 1][lm] = a4.y;
        As[lk + 2][lm] = a4.z; As[lk + 3][lm] = a4.w;
        Bs[lk + 0][lm] = b4.x; Bs[lk + 1][lm] = b4.y;
        Bs[lk + 2][lm] = b4.z; Bs[lk + 3][lm] = b4.w;
        __syncthreads();
        mm16(As, Bs, acc, ty, tx);
        __syncthreads();
    }
    int r = row0 + (ty << 2), c = col0 + (tx << 2);
    float q2v[4];
#pragma unroll
    for (int j = 0; j < 4; j++) q2v[j] = g_q2[b * LQ + c + j];
#pragma unroll
    for (int i = 0; i < 4; i++) {
        float ci = g_c1[b * LC + r + i];
        float4 o;
        o.x = acc[i][0] + ci + q2v[0];
        o.y = acc[i][1] + ci + q2v[1];
        o.z = acc[i][2] + ci + q2v[2];
        o.w = acc[i][3] + ci + q2v[3];
        *(float4*)(g_S + ((size_t)b * LC + r + i) * LQ + c) = o;
    }
}

// ---------------- K3: row softmax (axis j, mask = qmask) -> S1 --------------
__global__ void softmax_row_kernel(const float* __restrict__ qmask) {
    __shared__ float sred[64];
    int i = blockIdx.x, b = blockIdx.y;
    int t = threadIdx.x;
    const float* srow = g_S + ((size_t)b * LC + i) * LQ;
    float* drow = g_S1 + ((size_t)b * LC + i) * LQ;
    float m0 = qmask[b * LQ + t], m1 = qmask[b * LQ + t + 256];
    float x0 = srow[t] * m0 + (1.f - m0) * NEG_INF_F;
    float x1 = srow[t + 256] * m1 + (1.f - m1) * NEG_INF_F;
    float v = fmaxf(x0, x1);
    int lane = t & 31, wid = t >> 5;
#pragma unroll
    for (int o = 16; o; o >>= 1) v = fmaxf(v, __shfl_xor_sync(0xffffffffu, v, o));
    if (lane == 0) sred[wid] = v;
    __syncthreads();
    if (t < 32) {
        float w2 = (t < 8) ? sred[t] : -3e38f;
#pragma unroll
        for (int o = 4; o; o >>= 1) w2 = fmaxf(w2, __shfl_xor_sync(0xffffffffu, w2, o));
        if (t == 0) sred[32] = w2;
    }
    __syncthreads();
    float mx = sred[32];
    float e0 = __expf(x0 - mx), e1 = __expf(x1 - mx);
    v = e0 + e1;
#pragma unroll
    for (int o = 16; o; o >>= 1) v += __shfl_xor_sync(0xffffffffu, v, o);
    if (lane == 0) sred[wid] = v;
    __syncthreads();
    if (t < 32) {
        float w2 = (t < 8) ? sred[t] : 0.f;
#pragma unroll
        for (int o = 4; o; o >>= 1) w2 += __shfl_xor_sync(0xffffffffu, w2, o);
        if (t == 0) sred[33] = w2;
    }
    __syncthreads();
    float inv = 1.f / sred[33];
    drow[t] = e0 * inv;
    drow[t + 256] = e1 * inv;
}

// ---------------- K4: column softmax (axis i, mask = cmask) -> S2 -----------
__global__ void softmax_col_kernel(const float* __restrict__ cmask) {
    int j = blockIdx.x * blockDim.x + threadIdx.x;
    int b = blockIdx.y;
    const float* Sb = g_S + (size_t)b * LC * LQ;
    float* Ob = g_S2 + (size_t)b * LC * LQ;
    const float* cm = cmask + b * LC;
    float m = -3e38f, l = 0.f;
    for (int i = 0; i < LC; i++) {
        float cmi = cm[i];
        float x = Sb[(size_t)i * LQ + j] * cmi + (1.f - cmi) * NEG_INF_F;
        float nm = fmaxf(m, x);
        l = l * __expf(m - nm) + __expf(x - nm);
        m = nm;
    }
    float inv = 1.f / l;
    for (int i = 0; i < LC; i++) {
        float cmi = cm[i];
        float x = Sb[(size_t)i * LQ + j] * cmi + (1.f - cmi) * NEG_INF_F;
        Ob[(size_t)i * LQ + j] = __expf(x - m) * inv;
    }
}

// ---------------- K5/K7: NN GEMM  out = S1 @ B  (A=g_S1) --------------------
// which==0: B = Qin (param), out = g_A;  which==1: B = g_T, out = g_Bm
__global__ __launch_bounds__(256) void gemm_nn_kernel(const float* __restrict__ Bin,
                                                      int which) {
    __shared__ float As[16][64];
    __shared__ float Bs[16][64];
    const float* Bbase = which ? (const float*)g_T : Bin;
    float* Obase = which ? g_Bm : g_A;
    int b = blockIdx.z;
    int row0 = blockIdx.y << 6, col0 = blockIdx.x << 6;
    const float* Ag = g_S1 + (size_t)b * LC * LQ;
    const float* Bg = Bbase + (size_t)b * LQ * DD;
    float* Og = Obase + (size_t)b * LC * DD;
    int tid = threadIdx.x;
    int ty = tid >> 4, tx = tid & 15;
    int lm = tid >> 2, lk = (tid & 3) << 2;  // A-tile load
    int bk = tid >> 4, bn = (tid & 15) << 2; // B-tile load
    float acc[4][4] = {};
    for (int k0 = 0; k0 < LQ; k0 += 16) {
        float4 a4 = *(const float4*)(Ag + (size_t)(row0 + lm) * LQ + k0 + lk);
        float4 b4 = *(const float4*)(Bg + (size_t)(k0 + bk) * DD + col0 + bn);
        As[lk + 0][lm] = a4.x; As[lk + 1][lm] = a4.y;
        As[lk + 2][lm] = a4.z; As[lk + 3][lm] = a4.w;
        *(float4*)(&Bs[bk][bn]) = b4;
        __syncthreads();
        mm16(As, Bs, acc, ty, tx);
        __syncthreads();
    }
    int r = row0 + (ty << 2), c = col0 + (tx << 2);
#pragma unroll
    for (int i = 0; i < 4; i++) {
        float4 o = {acc[i][0], acc[i][1], acc[i][2], acc[i][3]};
        *(float4*)(Og + (size_t)(r + i) * DD + c) = o;
    }
}

// ---------------- K6: TN GEMM  g_T = S2^T @ C  ------------------------------
__global__ __launch_bounds__(256) void gemm_T_kernel(const float* __restrict__ Cin) {
    __shared__ float As[16][64];
    __shared__ float Bs[16][64];
    int b = blockIdx.z;
    int row0 = blockIdx.y << 6, col0 = blockIdx.x << 6;   // row = j, col = d
    const float* Ag = g_S2 + (size_t)b * LC * LQ;         // [K=LC][M=LQ]
    const float* Bg = Cin + (size_t)b * LC * DD;          // [K=LC][N=DD]
    int tid = threadIdx.x;
    int ty = tid >> 4, tx = tid & 15;
    int ak = tid >> 4, am = (tid & 15) << 2;
    float acc[4][4] = {};
    for (int k0 = 0; k0 < LC; k0 += 16) {
        float4 a4 = *(const float4*)(Ag + (size_t)(k0 + ak) * LQ + row0 + am);
        float4 b4 = *(const float4*)(Bg + (size_t)(k0 + ak) * DD + col0 + am);
        *(float4*)(&As[ak][am]) = a4;
        *(float4*)(&Bs[ak][am]) = b4;
        __syncthreads();
        mm16(As, Bs, acc, ty, tx);
        __syncthreads();
    }
    int r = row0 + (ty << 2), c = col0 + (tx << 2);
#pragma unroll
    for (int i = 0; i < 4; i++) {
        float4 o = {acc[i][0], acc[i][1], acc[i][2], acc[i][3]};
        *(float4*)(g_T + ((size_t)b * LQ + r + i) * DD + c) = o;
    }
}

// ---------------- K8: out = [C, A, C*A, C*Bm] @ out_w^T + out_b (NT) --------
__global__ __launch_bounds__(256) void final_kernel(const float* __restrict__ Cin,
                                                    const float* __restrict__ out_w,
                                                    const float* __restrict__ out_b,
                                                    float* __restrict__ out) {
    __shared__ float As[16][64];
    __shared__ float Bs[16][64];
    int row0 = blockIdx.y << 6;   // flat row in [0, BB*LC)
    int col0 = blockIdx.x << 6;
    int tid = threadIdx.x;
    int ty = tid >> 4, tx = tid & 15;
    int lm = tid >> 2, lk = (tid & 3) << 2;
    float acc[4][4] = {};
    for (int k0 = 0; k0 < 4 * DD; k0 += 16) {
        int chunk = k0 >> 9;          // uniform across block (16 | 512)
        int kk = k0 & (DD - 1);
        size_t aoff = (size_t)(row0 + lm) * DD + kk + lk;
        float4 a4;
        if (chunk == 0) {
            a4 = *(const float4*)(Cin + aoff);
        } else if (chunk == 1) {
            a4 = *(const float4*)(g_A + aoff);
        } else if (chunk == 2) {
            a4 = *(const float4*)(Cin + aoff);
            float4 x = *(const float4*)(g_A + aoff);
            a4.x *= x.x; a4.y *= x.y; a4.z *= x.z; a4.w *= x.w;
        } else {
            a4 = *(const float4*)(Cin + aoff);
            float4 x = *(const float4*)(g_Bm + aoff);
            a4.x *= x.x; a4.y *= x.y; a4.z *= x.z; a4.w *= x.w;
        }
        float4 b4 = *(const float4*)(out_w + (size_t)(col0 + lm) * (4 * DD) + k0 + lk);
        As[lk + 0][lm] = a4.x; As[lk + 1][lm] = a4.y;
        As[lk + 2][lm] = a4.z; As[lk + 3][lm] = a4.w;
        Bs[lk + 0][lm] = b4.x; Bs[lk + 1][lm] = b4.y;
        Bs[lk + 2][lm] = b4.z; Bs[lk + 3][lm] = b4.w;
        __syncthreads();
        mm16(As, Bs, acc, ty, tx);
        __syncthreads();
    }
    int r = row0 + (ty << 2), c = col0 + (tx << 2);
    float bb[4] = {out_b[c], out_b[c + 1], out_b[c + 2], out_b[c + 3]};
#pragma unroll
    for (int i = 0; i < 4; i++) {
        float4 o = {acc[i][0] + bb[0], acc[i][1] + bb[1],
                    acc[i][2] + bb[2], acc[i][3] + bb[3]};
        *(float4*)(out + (size_t)(r + i) * DD + c) = o;
    }
}

// ---------------- launch ----------------------------------------------------
extern "C" void kernel_launch(void* const* d_in, const int* in_sizes, int n_in,
                              void* d_out, int out_size) {
    const float* C      = (const float*)d_in[0];
    const float* Q      = (const float*)d_in[1];
    const float* cmask  = (const float*)d_in[2];
    const float* qmask  = (const float*)d_in[3];
    const float* w      = (const float*)d_in[4];
    const float* out_w  = (const float*)d_in[5];
    const float* out_b  = (const float*)d_in[6];
    float* out          = (float*)d_out;

    // K1: row dots (8 warps / block)
    rowdot_kernel<<<(BB * LC) / 8, 256>>>(C, w, 0, BB * LC);
    rowdot_kernel<<<(BB * LQ) / 8, 256>>>(Q, w + DD, 1, BB * LQ);

    // K2: S = (C*w3) @ Q^T + c1 + q2
    gemm_S_kernel<<<dim3(LQ / 64, LC / 64, BB), 256>>>(C, Q, w);

    // K3/K4: softmaxes
    softmax_row_kernel<<<dim3(LC, BB), 256>>>(qmask);
    softmax_col_kernel<<<dim3(LQ / 256, BB), 256>>>(cmask);

    // K5: A = S1 @ Q
    gemm_nn_kernel<<<dim3(DD / 64, LC / 64, BB), 256>>>(Q, 0);
    // K6: T = S2^T @ C
    gemm_T_kernel<<<dim3(DD / 64, LQ / 64, BB), 256>>>(C);
    // K7: Bm = S1 @ T
    gemm_nn_kernel<<<dim3(DD / 64, LC / 64, BB), 256>>>(Q, 1);

    // K8: output projection with on-the-fly concat features
    final_kernel<<<dim3(DD / 64, (BB * LC) / 64, 1), 256>>>(C, out_w, out_b, out);
}

// round 9
// speedup vs baseline: 1.4983x; 1.4983x over previous
#include <cuda_runtime.h>
#include <cuda_bf16.h>
#include <mma.h>
#include <stdint.h>
#include <math.h>

using namespace nvcuda;

#define BB 16
#define LC 1024
#define LQ 512
#define DD 512
#define NEG_INF_F (-1e30f)

typedef __nv_bfloat16 bf16;

// ======================= scratch (static device arrays) =====================
__device__ float g_c1[BB * LC];
__device__ float g_q2[BB * LQ];
__device__ float g_S [(size_t)BB * LC * LQ];   // logits
__device__ float g_S2[(size_t)BB * LC * LQ];   // col softmax fp32
__device__ float g_T [(size_t)BB * LQ * DD];   // S2^T C fp32

__device__ bf16 g_CWh[(size_t)BB * LC * DD], g_CWl[(size_t)BB * LC * DD];
__device__ bf16 g_Qh [(size_t)BB * LQ * DD], g_Ql [(size_t)BB * LQ * DD];
__device__ bf16 g_QTh[(size_t)BB * DD * LQ], g_QTl[(size_t)BB * DD * LQ];
__device__ bf16 g_CTh[(size_t)BB * DD * LC], g_CTl[(size_t)BB * DD * LC];
__device__ bf16 g_S1h[(size_t)BB * LC * LQ], g_S1l[(size_t)BB * LC * LQ];
__device__ bf16 g_S2Th[(size_t)BB * LQ * LC], g_S2Tl[(size_t)BB * LQ * LC];
__device__ bf16 g_TTh[(size_t)BB * DD * LQ], g_TTl[(size_t)BB * DD * LQ];
__device__ bf16 g_Wh [(size_t)DD * 4 * DD],  g_Wl [(size_t)DD * 4 * DD];
__device__ bf16 g_Xh [(size_t)BB * LC * 4 * DD], g_Xl[(size_t)BB * LC * 4 * DD];

// Device-side buffer resolution — NEVER pass __device__ symbols from host.
// ids: 0=CW 1=Q 2=QT 3=CT 4=S1 5=S2T 6=TT 7=W 8=X
__device__ __forceinline__ bf16* bufH(int i) {
    switch (i) {
        case 0: return g_CWh; case 1: return g_Qh;  case 2: return g_QTh;
        case 3: return g_CTh; case 4: return g_S1h; case 5: return g_S2Th;
        case 6: return g_TTh; case 7: return g_Wh;  default: return g_Xh;
    }
}
__device__ __forceinline__ bf16* bufL(int i) {
    switch (i) {
        case 0: return g_CWl; case 1: return g_Ql;  case 2: return g_QTl;
        case 3: return g_CTl; case 4: return g_S1l; case 5: return g_S2Tl;
        case 6: return g_TTl; case 7: return g_Wl;  default: return g_Xl;
    }
}

// ======================= helpers ============================================
__device__ __forceinline__ void bsplit(float x, bf16& h, bf16& l) {
    h = __float2bfloat16(x);
    l = __float2bfloat16(x - __bfloat162float(h));
}

// ======================= small kernels ======================================
__global__ void rowdot_kernel(const float* __restrict__ X, const float* __restrict__ w,
                              int which, int nrows) {
    float* out = which ? g_q2 : g_c1;
    int gw = (blockIdx.x * blockDim.x + threadIdx.x) >> 5;
    int lane = threadIdx.x & 31;
    if (gw >= nrows) return;
    const float* row = X + (size_t)gw * DD;
    float s = 0.f;
#pragma unroll 4
    for (int k = lane; k < DD; k += 32) s = fmaf(row[k], w[k], s);
#pragma unroll
    for (int o = 16; o; o >>= 1) s += __shfl_xor_sync(0xffffffffu, s, o);
    if (lane == 0) out[gw] = s;
}

__global__ void split_kernel(const float* __restrict__ src, int dstIdx,
                             size_t n, const float* __restrict__ scale) {
    size_t i = (size_t)blockIdx.x * blockDim.x + threadIdx.x;
    if (i >= n) return;
    float v = src[i];
    if (scale) v *= scale[i & (DD - 1)];
    bf16 h, l;
    bsplit(v, h, l);
    bufH(dstIdx)[i] = h;
    bufL(dstIdx)[i] = l;
}

__global__ void split_xc_kernel(const float* __restrict__ C) {
    size_t i = (size_t)blockIdx.x * blockDim.x + threadIdx.x;  // over BB*LC*DD
    size_t row = i >> 9;
    int c = (int)(i & (DD - 1));
    bsplit(C[i], g_Xh[row * (4 * DD) + c], g_Xl[row * (4 * DD) + c]);
}

// src fp32 [R x Cc] per batch -> dst bf16 hi/lo [Cc x R]
// srcSel: 0 = srcParam (harness ptr), 1 = g_S2, 2 = g_T
__global__ void transpose_split_kernel(const float* __restrict__ srcParam, int srcSel,
                                       int dstIdx, int R, int Cc) {
    __shared__ float t[32][33];
    const float* src = (srcSel == 0) ? srcParam : (srcSel == 1 ? g_S2 : g_T);
    bf16* h = bufH(dstIdx);
    bf16* l = bufL(dstIdx);
    int b = blockIdx.z;
    const float* S = src + (size_t)b * R * Cc;
    size_t ob = (size_t)b * R * Cc;
    int c0 = blockIdx.x * 32, r0 = blockIdx.y * 32;
    int tx = threadIdx.x, ty = threadIdx.y;
#pragma unroll
    for (int j = 0; j < 32; j += 8)
        t[ty + j][tx] = S[(size_t)(r0 + ty + j) * Cc + c0 + tx];
    __syncthreads();
#pragma unroll
    for (int j = 0; j < 32; j += 8) {
        float v = t[tx][ty + j];
        size_t o = ob + (size_t)(c0 + ty + j) * R + r0 + tx;
        bf16 hh, ll;
        bsplit(v, hh, ll);
        h[o] = hh;
        l[o] = ll;
    }
}

__global__ void softmax_row_kernel(const float* __restrict__ qmask) {
    __shared__ float sred[64];
    int i = blockIdx.x, b = blockIdx.y;
    int t = threadIdx.x;
    size_t base = ((size_t)b * LC + i) * LQ;
    const float* srow = g_S + base;
    float m0 = qmask[b * LQ + t], m1 = qmask[b * LQ + t + 256];
    float x0 = srow[t] * m0 + (1.f - m0) * NEG_INF_F;
    float x1 = srow[t + 256] * m1 + (1.f - m1) * NEG_INF_F;
    float v = fmaxf(x0, x1);
    int lane = t & 31, wid = t >> 5;
#pragma unroll
    for (int o = 16; o; o >>= 1) v = fmaxf(v, __shfl_xor_sync(0xffffffffu, v, o));
    if (lane == 0) sred[wid] = v;
    __syncthreads();
    if (t < 32) {
        float w2 = (t < 8) ? sred[t] : -3e38f;
#pragma unroll
        for (int o = 4; o; o >>= 1) w2 = fmaxf(w2, __shfl_xor_sync(0xffffffffu, w2, o));
        if (t == 0) sred[32] = w2;
    }
    __syncthreads();
    float mx = sred[32];
    float e0 = __expf(x0 - mx), e1 = __expf(x1 - mx);
    v = e0 + e1;
#pragma unroll
    for (int o = 16; o; o >>= 1) v += __shfl_xor_sync(0xffffffffu, v, o);
    if (lane == 0) sred[wid] = v;
    __syncthreads();
    if (t < 32) {
        float w2 = (t < 8) ? sred[t] : 0.f;
#pragma unroll
        for (int o = 4; o; o >>= 1) w2 += __shfl_xor_sync(0xffffffffu, w2, o);
        if (t == 0) sred[33] = w2;
    }
    __syncthreads();
    float inv = 1.f / sred[33];
    bsplit(e0 * inv, g_S1h[base + t], g_S1l[base + t]);
    bsplit(e1 * inv, g_S1h[base + t + 256], g_S1l[base + t + 256]);
}

__global__ void softmax_col_kernel(const float* __restrict__ cmask) {
    int j = blockIdx.x * blockDim.x + threadIdx.x;
    int b = blockIdx.y;
    const float* Sb = g_S + (size_t)b * LC * LQ;
    float* Ob = g_S2 + (size_t)b * LC * LQ;
    const float* cm = cmask + b * LC;
    float m = -3e38f, l = 0.f;
    for (int i = 0; i < LC; i++) {
        float cmi = cm[i];
        float x = Sb[(size_t)i * LQ + j] * cmi + (1.f - cmi) * NEG_INF_F;
        float nm = fmaxf(m, x);
        l = l * __expf(m - nm) + __expf(x - nm);
        m = nm;
    }
    float inv = 1.f / l;
    for (int i = 0; i < LC; i++) {
        float cmi = cm[i];
        float x = Sb[(size_t)i * LQ + j] * cmi + (1.f - cmi) * NEG_INF_F;
        Ob[(size_t)i * LQ + j] = __expf(x - m) * inv;
    }
}

// ======================= WMMA GEMM ==========================================
// D[128x128] per CTA; A,B bf16 hi/lo K-major [rows x K] row-major.
// bf16x3: D = Ah*Bh + Ah*Bl + Al*Bh, fp32 accumulate (wmma).
#define KC 32
#define LDT 40   // padded smem row stride in elements (80 B)

__device__ __forceinline__ void epi_pair(int mode, int b, int row, int col,
                                         float v0, float v1, float* outF,
                                         const float* Csrc, const float* bias) {
    if (mode == 0) {  // S logits += c1[row] + q2[col]
        size_t grow = (size_t)b * LC + row;
        float c1v = g_c1[b * LC + row];
        float2 o = make_float2(v0 + c1v + g_q2[b * LQ + col],
                               v1 + c1v + g_q2[b * LQ + col + 1]);
        *(float2*)(g_S + grow * LQ + col) = o;
    } else if (mode == 1) {  // plain fp32 (T)
        *(float2*)(g_T + ((size_t)b * LQ + row) * DD + col) = make_float2(v0, v1);
    } else if (mode == 2 || mode == 3) {  // X features
        size_t grow = (size_t)b * LC + row;
        const float* crow = Csrc + grow * DD + col;
        size_t xrow = grow * (size_t)(4 * DD);
        bf16 h0, l0, h1, l1;
        if (mode == 2) {
            bsplit(v0, h0, l0);
            bsplit(v1, h1, l1);
            *(__nv_bfloat162*)(g_Xh + xrow + DD + col) = __halves2bfloat162(h0, h1);
            *(__nv_bfloat162*)(g_Xl + xrow + DD + col) = __halves2bfloat162(l0, l1);
        }
        int off = (mode == 2) ? 2 * DD : 3 * DD;
        bsplit(crow[0] * v0, h0, l0);
        bsplit(crow[1] * v1, h1, l1);
        *(__nv_bfloat162*)(g_Xh + xrow + off + col) = __halves2bfloat162(h0, h1);
        *(__nv_bfloat162*)(g_Xl + xrow + off + col) = __halves2bfloat162(l0, l1);
    } else {  // mode 4: final + bias (row is global over BB*LC; outF = harness out)
        *(float2*)(outF + (size_t)row * DD + col) =
            make_float2(v0 + bias[col], v1 + bias[col + 1]);
    }
}

__global__ void __launch_bounds__(256)
wmma_gemm(int aIdx, int bIdx, size_t aStride, size_t bStride, int K, int mode,
          float* __restrict__ outH,
          const float* __restrict__ Csrc, const float* __restrict__ bias) {
    __shared__ __align__(32) bf16 sAh[128 * LDT], sAl[128 * LDT];
    __shared__ __align__(32) bf16 sBh[128 * LDT], sBl[128 * LDT];

    int tid = threadIdx.x, lane = tid & 31, wid = tid >> 5;
    int warp_m = wid & 1, warp_n = wid >> 1;  // 2 x 4 warps; warp tile 64 x 32
    int b = blockIdx.z;
    int row0 = blockIdx.y << 7, col0 = blockIdx.x << 7;

    const bf16* base[4];
    base[0] = bufH(aIdx) + (size_t)b * aStride + (size_t)row0 * K;
    base[1] = bufL(aIdx) + (size_t)b * aStride + (size_t)row0 * K;
    base[2] = bufH(bIdx) + (size_t)b * bStride + (size_t)col0 * K;
    base[3] = bufL(bIdx) + (size_t)b * bStride + (size_t)col0 * K;
    bf16* sptr[4] = {sAh, sAl, sBh, sBl};

    wmma::fragment<wmma::accumulator, 16, 16, 16, float> acc[4][2];
#pragma unroll
    for (int mi = 0; mi < 4; mi++)
#pragma unroll
        for (int nj = 0; nj < 2; nj++) wmma::fill_fragment(acc[mi][nj], 0.0f);

    int lrow = tid >> 1, lhalf = (tid & 1) << 4;  // 128 rows x 2 half-rows of 16

    for (int k0 = 0; k0 < K; k0 += KC) {
        __syncthreads();  // previous iteration's readers done
#pragma unroll
        for (int m = 0; m < 4; m++) {
            const bf16* g = base[m] + (size_t)lrow * K + k0 + lhalf;
            bf16* s = sptr[m] + lrow * LDT + lhalf;
            *(uint4*)s = *(const uint4*)g;
            *(uint4*)(s + 8) = *(const uint4*)(g + 8);
        }
        __syncthreads();

#pragma unroll
        for (int ks = 0; ks < KC; ks += 16) {
            wmma::fragment<wmma::matrix_b, 16, 16, 16, bf16, wmma::col_major> fbh[2], fbl[2];
#pragma unroll
            for (int nj = 0; nj < 2; nj++) {
                int nrow = warp_n * 32 + nj * 16;
                wmma::load_matrix_sync(fbh[nj], sBh + nrow * LDT + ks, LDT);
                wmma::load_matrix_sync(fbl[nj], sBl + nrow * LDT + ks, LDT);
            }
#pragma unroll
            for (int mi = 0; mi < 4; mi++) {
                int arow = warp_m * 64 + mi * 16;
                wmma::fragment<wmma::matrix_a, 16, 16, 16, bf16, wmma::row_major> fah, fal;
                wmma::load_matrix_sync(fah, sAh + arow * LDT + ks, LDT);
                wmma::load_matrix_sync(fal, sAl + arow * LDT + ks, LDT);
#pragma unroll
                for (int nj = 0; nj < 2; nj++) {
                    wmma::mma_sync(acc[mi][nj], fah, fbh[nj], acc[mi][nj]);
                    wmma::mma_sync(acc[mi][nj], fah, fbl[nj], acc[mi][nj]);
                    wmma::mma_sync(acc[mi][nj], fal, fbh[nj], acc[mi][nj]);
                }
            }
        }
    }
    __syncthreads();  // all compute done before staging reuse

    // ---- epilogue: stage each 16x16 acc tile through smem ----
    float* stag = reinterpret_cast<float*>(sAh) + wid * 256;  // 1KB per warp
    int prow = lane >> 1, pc0 = (lane & 1) << 3;
#pragma unroll
    for (int mi = 0; mi < 4; mi++)
#pragma unroll
        for (int nj = 0; nj < 2; nj++) {
            wmma::store_matrix_sync(stag, acc[mi][nj], 16, wmma::mem_row_major);
            __syncwarp();
            int rr = row0 + warp_m * 64 + mi * 16 + prow;
            int cc0 = col0 + warp_n * 32 + nj * 16 + pc0;
#pragma unroll
            for (int p = 0; p < 8; p += 2)
                epi_pair(mode, b, rr, cc0 + p,
                         stag[prow * 16 + pc0 + p], stag[prow * 16 + pc0 + p + 1],
                         outH, Csrc, bias);
            __syncwarp();
        }
}

// ======================= launch =============================================
extern "C" void kernel_launch(void* const* d_in, const int* in_sizes, int n_in,
                              void* d_out, int out_size) {
    const float* C     = (const float*)d_in[0];
    const float* Q     = (const float*)d_in[1];
    const float* cmask = (const float*)d_in[2];
    const float* qmask = (const float*)d_in[3];
    const float* w     = (const float*)d_in[4];
    const float* out_w = (const float*)d_in[5];
    const float* out_b = (const float*)d_in[6];
    float* out         = (float*)d_out;

    // row dots
    rowdot_kernel<<<(BB * LC) / 8, 256>>>(C, w, 0, BB * LC);
    rowdot_kernel<<<(BB * LQ) / 8, 256>>>(Q, w + DD, 1, BB * LQ);

    // operand prep (bf16 splits + transposes)
    {
        size_t n = (size_t)BB * LC * DD;
        split_kernel<<<(unsigned)((n + 255) / 256), 256>>>(C, 0 /*CW*/, n, w + 2 * DD);
        split_xc_kernel<<<(unsigned)((n + 255) / 256), 256>>>(C);
    }
    {
        size_t n = (size_t)BB * LQ * DD;
        split_kernel<<<(unsigned)((n + 255) / 256), 256>>>(Q, 1 /*Q*/, n, nullptr);
    }
    {
        size_t n = (size_t)DD * 4 * DD;
        split_kernel<<<(unsigned)((n + 255) / 256), 256>>>(out_w, 7 /*W*/, n, nullptr);
    }
    transpose_split_kernel<<<dim3(DD / 32, LQ / 32, BB), dim3(32, 8)>>>(Q, 0, 2 /*QT*/, LQ, DD);
    transpose_split_kernel<<<dim3(DD / 32, LC / 32, BB), dim3(32, 8)>>>(C, 0, 3 /*CT*/, LC, DD);

    // S = (C*w3) @ Q^T + c1 + q2
    wmma_gemm<<<dim3(LQ / 128, LC / 128, BB), 256>>>(
        0 /*CW*/, 1 /*Q*/, (size_t)LC * DD, (size_t)LQ * DD, DD, 0, nullptr, nullptr, nullptr);

    // softmaxes
    softmax_row_kernel<<<dim3(LC, BB), 256>>>(qmask);        // -> S1 bf16 hi/lo
    softmax_col_kernel<<<dim3(LQ / 256, BB), 256>>>(cmask);  // -> g_S2 fp32
    transpose_split_kernel<<<dim3(LQ / 32, LC / 32, BB), dim3(32, 8)>>>(nullptr, 1 /*g_S2*/, 5 /*S2T*/, LC, LQ);

    // T = S2^T @ C   (A = S2T [LQ x LC], B = CT [DD x LC])
    wmma_gemm<<<dim3(DD / 128, LQ / 128, BB), 256>>>(
        5 /*S2T*/, 3 /*CT*/, (size_t)LQ * LC, (size_t)DD * LC, LC, 1, nullptr, nullptr, nullptr);
    transpose_split_kernel<<<dim3(DD / 32, LQ / 32, BB), dim3(32, 8)>>>(nullptr, 2 /*g_T*/, 6 /*TT*/, LQ, DD);

    // A = S1 @ Q  -> X[:,512:1024] and C*A -> X[:,1024:1536]
    wmma_gemm<<<dim3(DD / 128, LC / 128, BB), 256>>>(
        4 /*S1*/, 2 /*QT*/, (size_t)LC * LQ, (size_t)DD * LQ, LQ, 2, nullptr, C, nullptr);

    // Bm = S1 @ T -> C*Bm -> X[:,1536:2048]
    wmma_gemm<<<dim3(DD / 128, LC / 128, BB), 256>>>(
        4 /*S1*/, 6 /*TT*/, (size_t)LC * LQ, (size_t)DD * LQ, LQ, 3, nullptr, C, nullptr);

    // out = X @ out_w^T + out_b   (M = BB*LC, N = DD, K = 4*DD)
    wmma_gemm<<<dim3(DD / 128, (BB * LC) / 128, 1), 256>>>(
        8 /*X*/, 7 /*W*/, 0, 0, 4 * DD, 4, out, nullptr, out_b);
}

// round 11
// speedup vs baseline: 1.7649x; 1.1779x over previous
#include <cuda_runtime.h>
#include <cuda_bf16.h>
#include <mma.h>
#include <stdint.h>
#include <math.h>

using namespace nvcuda;

#define BB 16
#define LC 1024
#define LQ 512
#define DD 512
#define NEG_INF_F (-1e30f)

typedef __nv_bfloat16 bf16;

// ======================= scratch (static device arrays) =====================
__device__ float g_c1[BB * LC];
__device__ float g_q2[BB * LQ];
__device__ float g_S [(size_t)BB * LC * LQ];   // logits
__device__ float g_S2[(size_t)BB * LC * LQ];   // col softmax fp32
__device__ float g_T [(size_t)BB * LQ * DD];   // S2^T C fp32

__device__ bf16 g_CWh[(size_t)BB * LC * DD], g_CWl[(size_t)BB * LC * DD];
__device__ bf16 g_Qh [(size_t)BB * LQ * DD], g_Ql [(size_t)BB * LQ * DD];
__device__ bf16 g_QTh[(size_t)BB * DD * LQ], g_QTl[(size_t)BB * DD * LQ];
__device__ bf16 g_CTh[(size_t)BB * DD * LC], g_CTl[(size_t)BB * DD * LC];
__device__ bf16 g_S1h[(size_t)BB * LC * LQ], g_S1l[(size_t)BB * LC * LQ];
__device__ bf16 g_S2Th[(size_t)BB * LQ * LC], g_S2Tl[(size_t)BB * LQ * LC];
__device__ bf16 g_TTh[(size_t)BB * DD * LQ], g_TTl[(size_t)BB * DD * LQ];
__device__ bf16 g_Wh [(size_t)DD * 4 * DD],  g_Wl [(size_t)DD * 4 * DD];
__device__ bf16 g_Xh [(size_t)BB * LC * 4 * DD], g_Xl[(size_t)BB * LC * 4 * DD];

// Device-side buffer resolution — NEVER pass __device__ symbols from host.
// ids: 0=CW 1=Q 2=QT 3=CT 4=S1 5=S2T 6=TT 7=W 8=X
__device__ __forceinline__ bf16* bufH(int i) {
    switch (i) {
        case 0: return g_CWh; case 1: return g_Qh;  case 2: return g_QTh;
        case 3: return g_CTh; case 4: return g_S1h; case 5: return g_S2Th;
        case 6: return g_TTh; case 7: return g_Wh;  default: return g_Xh;
    }
}
__device__ __forceinline__ bf16* bufL(int i) {
    switch (i) {
        case 0: return g_CWl; case 1: return g_Ql;  case 2: return g_QTl;
        case 3: return g_CTl; case 4: return g_S1l; case 5: return g_S2Tl;
        case 6: return g_TTl; case 7: return g_Wl;  default: return g_Xl;
    }
}

// ======================= helpers ============================================
__device__ __forceinline__ void bsplit(float x, bf16& h, bf16& l) {
    h = __float2bfloat16(x);
    l = __float2bfloat16(x - __bfloat162float(h));
}
#define CP_ASYNC(sa, ga) asm volatile( \
    "cp.async.cg.shared.global [%0], [%1], 16;" :: "r"(sa), "l"(ga))
#define CP_COMMIT() asm volatile("cp.async.commit_group;" ::: "memory")
#define CP_WAIT(n) asm volatile("cp.async.wait_group %0;" :: "n"(n) : "memory")
__device__ __forceinline__ uint32_t smem_u32(const void* p) {
    uint32_t a;
    asm("{ .reg .u64 t; cvta.to.shared.u64 t, %1; cvt.u32.u64 %0, t; }"
        : "=r"(a) : "l"(p));
    return a;
}

// ======================= small kernels ======================================
__global__ void rowdot_kernel(const float* __restrict__ X, const float* __restrict__ w,
                              int which, int nrows) {
    float* out = which ? g_q2 : g_c1;
    int gw = (blockIdx.x * blockDim.x + threadIdx.x) >> 5;
    int lane = threadIdx.x & 31;
    if (gw >= nrows) return;
    const float* row = X + (size_t)gw * DD;
    float s = 0.f;
#pragma unroll 4
    for (int k = lane; k < DD; k += 32) s = fmaf(row[k], w[k], s);
#pragma unroll
    for (int o = 16; o; o >>= 1) s += __shfl_xor_sync(0xffffffffu, s, o);
    if (lane == 0) out[gw] = s;
}

__device__ __forceinline__ void split2_store(bf16* h, bf16* l, size_t idx,
                                             float a, float b) {
    bf16 h0, l0, h1, l1;
    bsplit(a, h0, l0);
    bsplit(b, h1, l1);
    *(__nv_bfloat162*)(h + idx) = __halves2bfloat162(h0, h1);
    *(__nv_bfloat162*)(l + idx) = __halves2bfloat162(l0, l1);
}

// C: one read -> CW (scaled) split AND X[:,0:512] split
__global__ void split_c_kernel(const float* __restrict__ C, const float* __restrict__ w3) {
    size_t i = ((size_t)blockIdx.x * blockDim.x + threadIdx.x) * 4;  // < BB*LC*DD
    size_t row = i >> 9;
    int c = (int)(i & (DD - 1));
    float4 v = *(const float4*)(C + i);
    float4 s = *(const float4*)(w3 + c);
    split2_store(g_Xh, g_Xl, row * (4 * DD) + c, v.x, v.y);
    split2_store(g_Xh, g_Xl, row * (4 * DD) + c + 2, v.z, v.w);
    split2_store(g_CWh, g_CWl, i, v.x * s.x, v.y * s.y);
    split2_store(g_CWh, g_CWl, i + 2, v.z * s.z, v.w * s.w);
}

__global__ void split4_kernel(const float* __restrict__ src, int dstIdx, size_t n) {
    size_t i = ((size_t)blockIdx.x * blockDim.x + threadIdx.x) * 4;
    if (i >= n) return;
    float4 v = *(const float4*)(src + i);
    bf16* h = bufH(dstIdx);
    bf16* l = bufL(dstIdx);
    split2_store(h, l, i, v.x, v.y);
    split2_store(h, l, i + 2, v.z, v.w);
}

// src fp32 [R x Cc] per batch -> dst bf16 hi/lo [Cc x R]
// srcSel: 0 = srcParam (harness ptr), 1 = g_S2, 2 = g_T
__global__ void transpose_split_kernel(const float* __restrict__ srcParam, int srcSel,
                                       int dstIdx, int R, int Cc) {
    __shared__ float t[32][33];
    const float* src = (srcSel == 0) ? srcParam : (srcSel == 1 ? g_S2 : g_T);
    bf16* h = bufH(dstIdx);
    bf16* l = bufL(dstIdx);
    int b = blockIdx.z;
    const float* S = src + (size_t)b * R * Cc;
    size_t ob = (size_t)b * R * Cc;
    int c0 = blockIdx.x * 32, r0 = blockIdx.y * 32;
    int tx = threadIdx.x, ty = threadIdx.y;
#pragma unroll
    for (int j = 0; j < 32; j += 8)
        t[ty + j][tx] = S[(size_t)(r0 + ty + j) * Cc + c0 + tx];
    __syncthreads();
#pragma unroll
    for (int j = 0; j < 32; j += 8) {
        float v = t[tx][ty + j];
        size_t o = ob + (size_t)(c0 + ty + j) * R + r0 + tx;
        bf16 hh, ll;
        bsplit(v, hh, ll);
        h[o] = hh;
        l[o] = ll;
    }
}

__global__ void softmax_row_kernel(const float* __restrict__ qmask) {
    __shared__ float sred[64];
    int i = blockIdx.x, b = blockIdx.y;
    int t = threadIdx.x;
    size_t base = ((size_t)b * LC + i) * LQ;
    const float* srow = g_S + base;
    float m0 = qmask[b * LQ + t], m1 = qmask[b * LQ + t + 256];
    float x0 = srow[t] * m0 + (1.f - m0) * NEG_INF_F;
    float x1 = srow[t + 256] * m1 + (1.f - m1) * NEG_INF_F;
    float v = fmaxf(x0, x1);
    int lane = t & 31, wid = t >> 5;
#pragma unroll
    for (int o = 16; o; o >>= 1) v = fmaxf(v, __shfl_xor_sync(0xffffffffu, v, o));
    if (lane == 0) sred[wid] = v;
    __syncthreads();
    if (t < 32) {
        float w2 = (t < 8) ? sred[t] : -3e38f;
#pragma unroll
        for (int o = 4; o; o >>= 1) w2 = fmaxf(w2, __shfl_xor_sync(0xffffffffu, w2, o));
        if (t == 0) sred[32] = w2;
    }
    __syncthreads();
    float mx = sred[32];
    float e0 = __expf(x0 - mx), e1 = __expf(x1 - mx);
    v = e0 + e1;
#pragma unroll
    for (int o = 16; o; o >>= 1) v += __shfl_xor_sync(0xffffffffu, v, o);
    if (lane == 0) sred[wid] = v;
    __syncthreads();
    if (t < 32) {
        float w2 = (t < 8) ? sred[t] : 0.f;
#pragma unroll
        for (int o = 4; o; o >>= 1) w2 += __shfl_xor_sync(0xffffffffu, w2, o);
        if (t == 0) sred[33] = w2;
    }
    __syncthreads();
    float inv = 1.f / sred[33];
    bsplit(e0 * inv, g_S1h[base + t], g_S1l[base + t]);
    bsplit(e1 * inv, g_S1h[base + t + 256], g_S1l[base + t + 256]);
}

__global__ void softmax_col_kernel(const float* __restrict__ cmask) {
    int j = blockIdx.x * blockDim.x + threadIdx.x;
    int b = blockIdx.y;
    const float* Sb = g_S + (size_t)b * LC * LQ;
    float* Ob = g_S2 + (size_t)b * LC * LQ;
    const float* cm = cmask + b * LC;
    float m = -3e38f, l = 0.f;
    for (int i = 0; i < LC; i++) {
        float cmi = cm[i];
        float x = Sb[(size_t)i * LQ + j] * cmi + (1.f - cmi) * NEG_INF_F;
        float nm = fmaxf(m, x);
        l = l * __expf(m - nm) + __expf(x - nm);
        m = nm;
    }
    float inv = 1.f / l;
    for (int i = 0; i < LC; i++) {
        float cmi = cm[i];
        float x = Sb[(size_t)i * LQ + j] * cmi + (1.f - cmi) * NEG_INF_F;
        Ob[(size_t)i * LQ + j] = __expf(x - m) * inv;
    }
}

// ======================= WMMA GEMM (2-stage cp.async pipeline) ==============
// D[128x128] per CTA; A,B bf16 hi/lo K-major [rows x K] row-major.
// bf16x3: D = Ah*Bh + Ah*Bl + Al*Bh, fp32 accumulate (wmma).
#define KC 32
#define LDT 40                         // padded smem row stride (80 B)
#define PADB 80
#define TILEB (128 * PADB)             // 10240 B per matrix tile
#define STAGEB (4 * TILEB)             // Ah, Al, Bh, Bl = 40960 B
#define SMEM_GEMM (2 * STAGEB)         // 81920 B double-buffered

__device__ __forceinline__ void epi_pair(int mode, int b, int row, int col,
                                         float v0, float v1, float* outF,
                                         const float* Csrc, const float* bias) {
    if (mode == 0) {  // S logits += c1[row] + q2[col]
        size_t grow = (size_t)b * LC + row;
        float c1v = g_c1[b * LC + row];
        float2 o = make_float2(v0 + c1v + g_q2[b * LQ + col],
                               v1 + c1v + g_q2[b * LQ + col + 1]);
        *(float2*)(g_S + grow * LQ + col) = o;
    } else if (mode == 1) {  // plain fp32 (T)
        *(float2*)(g_T + ((size_t)b * LQ + row) * DD + col) = make_float2(v0, v1);
    } else if (mode == 2 || mode == 3) {  // X features
        size_t grow = (size_t)b * LC + row;
        const float* crow = Csrc + grow * DD + col;
        size_t xrow = grow * (size_t)(4 * DD);
        bf16 h0, l0, h1, l1;
        if (mode == 2) {
            bsplit(v0, h0, l0);
            bsplit(v1, h1, l1);
            *(__nv_bfloat162*)(g_Xh + xrow + DD + col) = __halves2bfloat162(h0, h1);
            *(__nv_bfloat162*)(g_Xl + xrow + DD + col) = __halves2bfloat162(l0, l1);
        }
        int off = (mode == 2) ? 2 * DD : 3 * DD;
        bsplit(crow[0] * v0, h0, l0);
        bsplit(crow[1] * v1, h1, l1);
        *(__nv_bfloat162*)(g_Xh + xrow + off + col) = __halves2bfloat162(h0, h1);
        *(__nv_bfloat162*)(g_Xl + xrow + off + col) = __halves2bfloat162(l0, l1);
    } else {  // mode 4: final + bias (row is global over BB*LC; outF = harness out)
        *(float2*)(outF + (size_t)row * DD + col) =
            make_float2(v0 + bias[col], v1 + bias[col + 1]);
    }
}

__global__ void __launch_bounds__(256)
wmma_gemm(int aIdx, int bIdx, size_t aStride, size_t bStride, int K, int mode,
          float* __restrict__ outH,
          const float* __restrict__ Csrc, const float* __restrict__ bias) {
    extern __shared__ __align__(16) char dsm[];
    int tid = threadIdx.x, lane = tid & 31, wid = tid >> 5;
    int warp_m = wid & 1, warp_n = wid >> 1;  // 2 x 4 warps; warp tile 64 x 32
    int b = blockIdx.z;
    int row0 = blockIdx.y << 7, col0 = blockIdx.x << 7;

    const bf16* base[4];
    base[0] = bufH(aIdx) + (size_t)b * aStride + (size_t)row0 * K;
    base[1] = bufL(aIdx) + (size_t)b * aStride + (size_t)row0 * K;
    base[2] = bufH(bIdx) + (size_t)b * bStride + (size_t)col0 * K;
    base[3] = bufL(bIdx) + (size_t)b * bStride + (size_t)col0 * K;

    uint32_t sb = smem_u32(dsm);
    wmma::fragment<wmma::accumulator, 16, 16, 16, float> acc[4][2];
#pragma unroll
    for (int mi = 0; mi < 4; mi++)
#pragma unroll
        for (int nj = 0; nj < 2; nj++) wmma::fill_fragment(acc[mi][nj], 0.0f);

    const int KT = K / KC;
    int lrow = tid >> 1;           // 0..127
    int lcc0 = (tid & 1) << 1;     // chunk index {0,2}

#define ISSUE(kt, st) do {                                                     \
        int _k0 = (kt) * KC;                                                   \
        uint32_t _s0 = sb + (st) * STAGEB;                                     \
        _Pragma("unroll")                                                      \
        for (int m = 0; m < 4; m++) {                                          \
            const bf16* _g = base[m] + (size_t)lrow * K + _k0;                 \
            uint32_t _sm = _s0 + m * TILEB + lrow * PADB;                      \
            CP_ASYNC(_sm + lcc0 * 16, _g + lcc0 * 8);                          \
            CP_ASYNC(_sm + (lcc0 + 1) * 16, _g + (lcc0 + 1) * 8);              \
        }                                                                      \
        CP_COMMIT();                                                           \
    } while (0)

    ISSUE(0, 0);

    for (int kt = 0; kt < KT; kt++) {
        int st = kt & 1;
        if (kt + 1 < KT) {
            ISSUE(kt + 1, st ^ 1);
            CP_WAIT(1);
        } else {
            CP_WAIT(0);
        }
        __syncthreads();  // cp.async data visible to all warps

        const bf16* sAh = (const bf16*)(dsm + st * STAGEB + 0 * TILEB);
        const bf16* sAl = (const bf16*)(dsm + st * STAGEB + 1 * TILEB);
        const bf16* sBh = (const bf16*)(dsm + st * STAGEB + 2 * TILEB);
        const bf16* sBl = (const bf16*)(dsm + st * STAGEB + 3 * TILEB);

#pragma unroll
        for (int ks = 0; ks < KC; ks += 16) {
            wmma::fragment<wmma::matrix_b, 16, 16, 16, bf16, wmma::col_major> fbh[2], fbl[2];
#pragma unroll
            for (int nj = 0; nj < 2; nj++) {
                int nrow = warp_n * 32 + nj * 16;
                wmma::load_matrix_sync(fbh[nj], sBh + nrow * LDT + ks, LDT);
                wmma::load_matrix_sync(fbl[nj], sBl + nrow * LDT + ks, LDT);
            }
#pragma unroll
            for (int mi = 0; mi < 4; mi++) {
                int arow = warp_m * 64 + mi * 16;
                wmma::fragment<wmma::matrix_a, 16, 16, 16, bf16, wmma::row_major> fah, fal;
                wmma::load_matrix_sync(fah, sAh + arow * LDT + ks, LDT);
                wmma::load_matrix_sync(fal, sAl + arow * LDT + ks, LDT);
#pragma unroll
                for (int nj = 0; nj < 2; nj++) {
                    wmma::mma_sync(acc[mi][nj], fah, fbh[nj], acc[mi][nj]);
                    wmma::mma_sync(acc[mi][nj], fah, fbl[nj], acc[mi][nj]);
                    wmma::mma_sync(acc[mi][nj], fal, fbh[nj], acc[mi][nj]);
                }
            }
        }
        __syncthreads();  // compute done before next ISSUE overwrites this stage
    }

    // ---- epilogue: stage each 16x16 acc tile through smem ----
    float* stag = reinterpret_cast<float*>(dsm) + wid * 256;  // 1KB per warp
    int prow = lane >> 1, pc0 = (lane & 1) << 3;
#pragma unroll
    for (int mi = 0; mi < 4; mi++)
#pragma unroll
        for (int nj = 0; nj < 2; nj++) {
            wmma::store_matrix_sync(stag, acc[mi][nj], 16, wmma::mem_row_major);
            __syncwarp();
            int rr = row0 + warp_m * 64 + mi * 16 + prow;
            int cc0 = col0 + warp_n * 32 + nj * 16 + pc0;
#pragma unroll
            for (int p = 0; p < 8; p += 2)
                epi_pair(mode, b, rr, cc0 + p,
                         stag[prow * 16 + pc0 + p], stag[prow * 16 + pc0 + p + 1],
                         outH, Csrc, bias);
            __syncwarp();
        }
}

// ======================= launch =============================================
extern "C" void kernel_launch(void* const* d_in, const int* in_sizes, int n_in,
                              void* d_out, int out_size) {
    const float* C     = (const float*)d_in[0];
    const float* Q     = (const float*)d_in[1];
    const float* cmask = (const float*)d_in[2];
    const float* qmask = (const float*)d_in[3];
    const float* w     = (const float*)d_in[4];
    const float* out_w = (const float*)d_in[5];
    const float* out_b = (const float*)d_in[6];
    float* out         = (float*)d_out;

    static int smem_set = 0;
    if (!smem_set) {
        cudaFuncSetAttribute(wmma_gemm, cudaFuncAttributeMaxDynamicSharedMemorySize,
                             SMEM_GEMM);
        smem_set = 1;
    }

    // row dots
    rowdot_kernel<<<(BB * LC) / 8, 256>>>(C, w, 0, BB * LC);
    rowdot_kernel<<<(BB * LQ) / 8, 256>>>(Q, w + DD, 1, BB * LQ);

    // operand prep (bf16 splits + transposes)
    {
        size_t n = (size_t)BB * LC * DD;           // 8388608
        split_c_kernel<<<(unsigned)(n / 1024), 256>>>(C, w + 2 * DD);
    }
    {
        size_t n = (size_t)BB * LQ * DD;
        split4_kernel<<<(unsigned)(n / 1024), 256>>>(Q, 1 /*Q*/, n);
    }
    {
        size_t n = (size_t)DD * 4 * DD;
        split4_kernel<<<(unsigned)(n / 1024), 256>>>(out_w, 7 /*W*/, n);
    }
    transpose_split_kernel<<<dim3(DD / 32, LQ / 32, BB), dim3(32, 8)>>>(Q, 0, 2 /*QT*/, LQ, DD);
    transpose_split_kernel<<<dim3(DD / 32, LC / 32, BB), dim3(32, 8)>>>(C, 0, 3 /*CT*/, LC, DD);

    // S = (C*w3) @ Q^T + c1 + q2
    wmma_gemm<<<dim3(LQ / 128, LC / 128, BB), 256, SMEM_GEMM>>>(
        0 /*CW*/, 1 /*Q*/, (size_t)LC * DD, (size_t)LQ * DD, DD, 0, nullptr, nullptr, nullptr);

    // softmaxes
    softmax_row_kernel<<<dim3(LC, BB), 256>>>(qmask);        // -> S1 bf16 hi/lo
    softmax_col_kernel<<<dim3(LQ / 256, BB), 256>>>(cmask);  // -> g_S2 fp32
    transpose_split_kernel<<<dim3(LQ / 32, LC / 32, BB), dim3(32, 8)>>>(nullptr, 1 /*g_S2*/, 5 /*S2T*/, LC, LQ);

    // T = S2^T @ C   (A = S2T [LQ x LC], B = CT [DD x LC])
    wmma_gemm<<<dim3(DD / 128, LQ / 128, BB), 256, SMEM_GEMM>>>(
        5 /*S2T*/, 3 /*CT*/, (size_t)LQ * LC, (size_t)DD * LC, LC, 1, nullptr, nullptr, nullptr);
    transpose_split_kernel<<<dim3(DD / 32, LQ / 32, BB), dim3(32, 8)>>>(nullptr, 2 /*g_T*/, 6 /*TT*/, LQ, DD);

    // A = S1 @ Q  -> X[:,512:1024] and C*A -> X[:,1024:1536]
    wmma_gemm<<<dim3(DD / 128, LC / 128, BB), 256, SMEM_GEMM>>>(
        4 /*S1*/, 2 /*QT*/, (size_t)LC * LQ, (size_t)DD * LQ, LQ, 2, nullptr, C, nullptr);

    // Bm = S1 @ T -> C*Bm -> X[:,1536:2048]
    wmma_gemm<<<dim3(DD / 128, LC / 128, BB), 256, SMEM_GEMM>>>(
        4 /*S1*/, 6 /*TT*/, (size_t)LC * LQ, (size_t)DD * LQ, LQ, 3, nullptr, C, nullptr);

    // out = X @ out_w^T + out_b   (M = BB*LC, N = DD, K = 4*DD)
    wmma_gemm<<<dim3(DD / 128, (BB * LC) / 128, 1), 256, SMEM_GEMM>>>(
        8 /*X*/, 7 /*W*/, 0, 0, 4 * DD, 4, out, nullptr, out_b);
}